// round 12
// baseline (speedup 1.0000x reference)
#include <cuda_runtime.h>
#include <cuda_fp16.h>
#include <math.h>
#include <stdint.h>

constexpr int B_ = 8;
constexpr int N_ = 512;
constexpr int D_ = 256;

constexpr int CLUSTER  = 8;
constexpr int CHUNK    = 32;   // D/CLUSTER
constexpr int IOU_ROWS = 64;   // 2D/CLUSTER
constexpr int COU_ROWS = 32;   // D/CLUSTER
constexpr int MTHREADS = 256;

// ---- device scratch ----
__device__ __align__(128) float g_dinv[B_ * N_];
__device__ __align__(128) float g_normT[B_ * N_ * N_];
__device__ __align__(128) float g_pre_iou[B_ * N_ * 2 * D_];
__device__ __align__(128) float g_pre_cou[B_ * N_ * D_];

__device__ __forceinline__ float fast_tanh(float x) {
    float r;
    asm("tanh.approx.f32 %0, %1;" : "=f"(r) : "f"(x));
    return r;
}
__device__ __forceinline__ float fast_sigmoid(float x) {
    return 0.5f + 0.5f * fast_tanh(0.5f * x);
}

// ---------------- dinv ----------------
__global__ void k_dinv(const float* __restrict__ adj) {
    int bi = blockIdx.x;
    const float* row = adj + (size_t)bi * N_;
    float s = 0.f;
    for (int j = threadIdx.x; j < N_; j += blockDim.x) s += row[j];
    __shared__ float sm[8];
    #pragma unroll
    for (int o = 16; o; o >>= 1) s += __shfl_down_sync(~0u, s, o);
    if ((threadIdx.x & 31) == 0) sm[threadIdx.x >> 5] = s;
    __syncthreads();
    if (threadIdx.x == 0) {
        float v = 0.f;
        for (int w = 0; w < 8; w++) v += sm[w];
        g_dinv[bi] = (v != 0.f) ? (1.f / v) : 0.f;
    }
}

// ---------------- normT[b][i][j] = adj[b][j][i] * dinv[b][i] ----------------
__global__ void k_transpose(const float* __restrict__ adj) {
    __shared__ float tile[32][33];
    int b = blockIdx.z;
    int i0 = blockIdx.x * 32, j0 = blockIdx.y * 32;
    int tx = threadIdx.x, ty = threadIdx.y;
    const float* A = adj + (size_t)b * N_ * N_;
    #pragma unroll
    for (int q = 0; q < 32; q += 8)
        tile[ty + q][tx] = A[(size_t)(j0 + ty + q) * N_ + i0 + tx];
    __syncthreads();
    float* T = g_normT + (size_t)b * N_ * N_;
    #pragma unroll
    for (int q = 0; q < 32; q += 8) {
        int i = i0 + ty + q;
        T[(size_t)i * N_ + j0 + tx] = tile[tx][ty + q] * g_dinv[b * N_ + i];
    }
}

// -------- fused pre GEMM: blocks 0-3 -> iou tile (P=512), 4-5 -> cou tile (P=256)
__global__ void k_gemm_fused(const float* __restrict__ X,
                             const float* __restrict__ Wi,
                             const float* __restrict__ bi1,
                             const float* __restrict__ bi2,
                             const float* __restrict__ Wc,
                             const float* __restrict__ bc1,
                             const float* __restrict__ bc2) {
    constexpr int BM = 128, BP = 128, BK = 16;
    __shared__ float As[BK][BM];
    __shared__ float Bs[BK][BP];

    const bool is_iou = (blockIdx.x < 4);
    const float* W  = is_iou ? Wi : Wc;
    const float* b1 = is_iou ? bi1 : bc1;
    const float* b2 = is_iou ? bi2 : bc2;
    float* C        = is_iou ? g_pre_iou : g_pre_cou;
    const int P     = is_iou ? 2 * D_ : D_;
    const int p0    = (is_iou ? blockIdx.x : blockIdx.x - 4) * BP;
    const int m0    = blockIdx.y * BM;

    int t = threadIdx.x;
    int tx = t % 16, ty = t / 16;
    float acc[8][8] = {};
    int lrow = t >> 2, lkv = (t & 3) * 4;

    for (int k0 = 0; k0 < D_; k0 += BK) {
        #pragma unroll
        for (int r = 0; r < BM; r += 64) {
            float4 v = *(const float4*)&X[(size_t)(m0 + lrow + r) * D_ + k0 + lkv];
            As[lkv + 0][lrow + r] = v.x; As[lkv + 1][lrow + r] = v.y;
            As[lkv + 2][lrow + r] = v.z; As[lkv + 3][lrow + r] = v.w;
        }
        #pragma unroll
        for (int r = 0; r < BP; r += 64) {
            float4 v = *(const float4*)&W[(size_t)(p0 + lrow + r) * D_ + k0 + lkv];
            Bs[lkv + 0][lrow + r] = v.x; Bs[lkv + 1][lrow + r] = v.y;
            Bs[lkv + 2][lrow + r] = v.z; Bs[lkv + 3][lrow + r] = v.w;
        }
        __syncthreads();
        #pragma unroll
        for (int k = 0; k < BK; k++) {
            float a[8], bb[8];
            *(float4*)&a[0]  = *(const float4*)&As[k][ty * 8];
            *(float4*)&a[4]  = *(const float4*)&As[k][ty * 8 + 4];
            *(float4*)&bb[0] = *(const float4*)&Bs[k][tx * 8];
            *(float4*)&bb[4] = *(const float4*)&Bs[k][tx * 8 + 4];
            #pragma unroll
            for (int im = 0; im < 8; im++)
                #pragma unroll
                for (int ip = 0; ip < 8; ip++)
                    acc[im][ip] += a[im] * bb[ip];
        }
        __syncthreads();
    }
    int pbase = p0 + tx * 8;
    float bs[8];
    #pragma unroll
    for (int ip = 0; ip < 8; ip++) bs[ip] = b1[pbase + ip] + b2[pbase + ip];
    #pragma unroll
    for (int im = 0; im < 8; im++) {
        size_t off = (size_t)(m0 + ty * 8 + im) * P + pbase;
        #pragma unroll
        for (int ip = 0; ip < 8; ip++) C[off + ip] = acc[im][ip] + bs[ip];
    }
}

// ---------------- main sequential cluster kernel (cluster = 8) ----------------
// SMEM byte offsets (R10 layout + 2 mbarriers)
constexpr int H_OFF    = 0;        // float[512*32]  65536
constexpr int ROW_OFF  = 65536;    // float[2*512]    4096
constexpr int XPAR_OFF = 69632;    // float[2*256]    2048
constexpr int V_OFF    = 71680;    // float[256]      1024
constexpr int Z_OFF    = 72704;    // float[256]      1024
constexpr int RED_OFF  = 73728;    // float[512]      2048
constexpr int SRED_OFF = 75776;    // float[32*32]    4096
constexpr int S1_OFF   = 79872;    // float[4*32]      512
constexpr int HNEW_OFF = 80384;    // float[32]        128
constexpr int BARA_B   = 80512;    // mbarrier          8
constexpr int BARB_B   = 80520;    // mbarrier          8
constexpr int WIOU_OFF = 80640;    // half[256*64]   32768
constexpr int WCOU_OFF = 113408;   // half[256*32]   16384
constexpr int SMEM_BYTES = 129792;

__device__ __forceinline__ void bcast_f32(float* localp, float val) {
    uint32_t l = (uint32_t)__cvta_generic_to_shared(localp);
    uint32_t bits = __float_as_uint(val);
    #pragma unroll
    for (int dst = 0; dst < CLUSTER; dst++) {
        uint32_t r;
        asm("mapa.shared::cluster.u32 %0, %1, %2;" : "=r"(r) : "r"(l), "r"(dst));
        asm volatile("st.shared::cluster.u32 [%0], %1;" :: "r"(r), "r"(bits));
    }
}

// elected-thread: one release-arrive on this barrier in every cluster CTA (8 total)
__device__ __forceinline__ void mbar_arrive_all(uint32_t localbar) {
    #pragma unroll
    for (int dst = 0; dst < CLUSTER; dst++) {
        uint32_t r;
        asm("mapa.shared::cluster.u32 %0, %1, %2;" : "=r"(r) : "r"(localbar), "r"(dst));
        asm volatile("mbarrier.arrive.release.cluster.shared::cluster.b64 _, [%0];"
                     :: "r"(r) : "memory");
    }
}

// consumer: wait on local barrier for given phase parity (acquire, cluster scope)
__device__ __forceinline__ void mbar_wait(uint32_t bar, int parity) {
    asm volatile(
        "{\n\t"
        ".reg .pred P;\n\t"
        "WAITLOOP_%=:\n\t"
        "mbarrier.try_wait.parity.acquire.cluster.shared::cta.b64 P, [%0], %1, 0x989680;\n\t"
        "@P bra.uni DONE_%=;\n\t"
        "bra.uni WAITLOOP_%=;\n\t"
        "DONE_%=:\n\t"
        "}" :: "r"(bar), "r"(parity) : "memory");
}

extern __shared__ char smem_raw[];

__global__ void __cluster_dims__(CLUSTER, 1, 1) __launch_bounds__(MTHREADS, 1)
k_main(const float* __restrict__ h_e,
       const float* __restrict__ W_iouh,
       const float* __restrict__ W_couh,
       float* __restrict__ out) {
    float* h_sm   = (float*)(smem_raw + H_OFF);     // [512][32]
    float* row_sm = (float*)(smem_raw + ROW_OFF);   // [2][512]
    float* xpar   = (float*)(smem_raw + XPAR_OFF);  // [2][256]
    float* vbuf   = (float*)(smem_raw + V_OFF);
    float* zbuf   = (float*)(smem_raw + Z_OFF);
    float* red    = (float*)(smem_raw + RED_OFF);   // [512]
    float* sred   = (float*)(smem_raw + SRED_OFF);  // [32][32]
    float* s1     = (float*)(smem_raw + S1_OFF);    // [4][32]
    float* hnew   = (float*)(smem_raw + HNEW_OFF);  // [32]
    __half* wiou  = (__half*)(smem_raw + WIOU_OFF); // [256][64] d-major
    __half* wcou  = (__half*)(smem_raw + WCOU_OFF); // [256][32] d-major
    const __half2* wiou2 = (const __half2*)wiou;
    const __half2* wcou2 = (const __half2*)wcou;

    const int t = threadIdx.x;
    const int rank = blockIdx.x % CLUSTER;
    const int b = blockIdx.x / CLUSTER;

    const uint32_t smem_base = (uint32_t)__cvta_generic_to_shared(smem_raw);
    const uint32_t barA = smem_base + BARA_B;
    const uint32_t barB = smem_base + BARB_B;

    // skip-one aggregation into sred (R10 form: 32 groups x 16 rows)
    auto sgemv = [&](const float* rowp, int skip) {
        int c4 = (t & 7) * 4, g = t >> 3;
        float4 acc = make_float4(0.f, 0.f, 0.f, 0.f);
        #pragma unroll
        for (int jj = 0; jj < 16; jj++) {
            int r = g + 32 * jj;
            if (r != skip) {
                float rv = rowp[r];
                float4 hv = *(const float4*)&h_sm[r * CHUNK + c4];
                acc.x += rv * hv.x; acc.y += rv * hv.y;
                acc.z += rv * hv.z; acc.w += rv * hv.w;
            }
        }
        *(float4*)&sred[g * CHUNK + c4] = acc;
    };

    // ---- init: barriers (count = 8: one elected arrive per CTA) ----
    if (t == 0) {
        asm volatile("mbarrier.init.shared.b64 [%0], %1;" :: "r"(barA), "r"((uint32_t)CLUSTER) : "memory");
        asm volatile("mbarrier.init.shared.b64 [%0], %1;" :: "r"(barB), "r"((uint32_t)CLUSTER) : "memory");
    }
    {   // h chunk, fp16 weight slices, rows 0/1
        const float* src = h_e + (size_t)b * N_ * D_ + rank * CHUNK;
        for (int idx = t; idx < N_ * CHUNK; idx += MTHREADS) {
            int j = idx / CHUNK, c = idx % CHUNK;
            h_sm[j * CHUNK + c] = src[(size_t)j * D_ + c];
        }
        const float* ws = W_iouh + (size_t)(rank * IOU_ROWS) * D_;
        for (int idx = t; idx < IOU_ROWS * D_; idx += MTHREADS) {
            int p = idx / D_, d = idx % D_;
            wiou[d * IOU_ROWS + p] = __float2half(ws[idx]);
        }
        const float* wc = W_couh + (size_t)(rank * COU_ROWS) * D_;
        for (int idx = t; idx < COU_ROWS * D_; idx += MTHREADS) {
            int p = idx / D_, d = idx % D_;
            wcou[d * COU_ROWS + p] = __float2half(wc[idx]);
        }
        if (t < 128) {
            *(float4*)&row_sm[t * 4] =
                *(const float4*)&g_normT[((size_t)b * N_) * N_ + t * 4];
            *(float4*)&row_sm[512 + t * 4] =
                *(const float4*)&g_normT[((size_t)b * N_ + 1) * N_ + t * 4];
        }
    }
    __syncthreads();
    // all mbarriers initialized cluster-wide before any remote arrive
    asm volatile("barrier.cluster.arrive.aligned;" ::: "memory");
    asm volatile("barrier.cluster.wait.aligned;" ::: "memory");

    int pA = 0, pB = 0;
    float pre = 0.f, pre2 = 0.f;

    // ---- bootstrap: x_par_0 ----
    sgemv(&row_sm[0], -1);
    __syncthreads();
    if (t < 128) {
        int c = t & 31, q = t >> 5;
        float s = 0.f;
        #pragma unroll
        for (int k = 0; k < 8; k++) s += sred[(q * 8 + k) * CHUNK + c];
        s1[q * CHUNK + c] = s;
    }
    __syncthreads();
    if (t < CHUNK) {
        float s = s1[t] + s1[32 + t] + s1[64 + t] + s1[96 + t];
        bcast_f32(&xpar[rank * CHUNK + t], s);
    }
    __syncthreads();
    if (t == 0) mbar_arrive_all(barA);
    if (t < IOU_ROWS)
        pre = g_pre_iou[((size_t)b * N_) * (2 * D_) + rank * IOU_ROWS + t];
    if (t < COU_ROWS)
        pre2 = g_pre_cou[((size_t)b * N_) * D_ + rank * COU_ROWS + t];
    mbar_wait(barA, pA); pA ^= 1;   // x_par_0 visible cluster-wide

    for (int i = 0; i < N_; i++) {
        const int cur = i & 1;
        const int nxt = cur ^ 1;
        const float* xp_cur = &xpar[cur * D_];
        const float* nrow = &row_sm[nxt * N_];  // row_{i+1}

        // ---- phase 2: iou GEMV (fp16 weights, fp32 acc) ----
        {
            int pp = t & 31, q = t >> 5;  // 8 d-groups of 32
            float a0 = 0.f, a1 = 0.f;
            const float* xp = xp_cur + q * 32;
            #pragma unroll
            for (int dd = 0; dd < 32; dd++) {
                float xv = xp[dd];
                float2 wf = __half22float2(wiou2[(q * 32 + dd) * 32 + pp]);
                a0 += xv * wf.x; a1 += xv * wf.y;
            }
            red[q * IOU_ROWS + 2 * pp]     = a0;
            red[q * IOU_ROWS + 2 * pp + 1] = a1;
        }
        __syncthreads();
        if (t < IOU_ROWS) {
            float s = pre;
            #pragma unroll
            for (int q = 0; q < 8; q++) s += red[q * IOU_ROWS + t];
            float sg = fast_sigmoid(s);
            if (rank < 4) {
                int gp = rank * IOU_ROWS + t;
                bcast_f32(&vbuf[gp], xp_cur[gp] * sg);
            } else {
                bcast_f32(&zbuf[(rank - 4) * IOU_ROWS + t], sg);
            }
        }
        __syncthreads();
        if (t == 0) mbar_arrive_all(barB);
        // hide the big aggregation for x_par_{i+1} behind the v/z sync
        if (i + 1 < N_) sgemv(nrow, i);
        mbar_wait(barB, pB); pB ^= 1;   // v, z visible cluster-wide

        // ---- phase 3: couh GEMV + tanh + update ----
        {
            int pp = t & 15, q = t >> 4;  // 16 d-groups of 16
            float a0 = 0.f, a1 = 0.f;
            const float* vp = &vbuf[q * 16];
            #pragma unroll
            for (int dd = 0; dd < 16; dd++) {
                float vv = vp[dd];
                float2 wf = __half22float2(wcou2[(q * 16 + dd) * 16 + pp]);
                a0 += vv * wf.x; a1 += vv * wf.y;
            }
            red[q * COU_ROWS + 2 * pp]     = a0;
            red[q * COU_ROWS + 2 * pp + 1] = a1;
        }
        __syncthreads();
        if (t < COU_ROWS) {
            float s = pre2;
            #pragma unroll
            for (int q = 0; q < 16; q++) s += red[q * COU_ROWS + t];
            float hc  = fast_tanh(s);
            float xpv = xp_cur[rank * COU_ROWS + t];
            float zz  = zbuf[rank * COU_ROWS + t];
            float hn  = zz * xpv + (1.f - zz) * hc;
            h_sm[i * CHUNK + t] = hn;
            hnew[t] = hn;
            out[((size_t)b * N_ + i) * D_ + rank * COU_ROWS + t] = hn;
        }
        __syncthreads();  // hnew + sred stores visible

        if (i + 1 < N_) {
            if (t < 128) {
                int c = t & 31, q = t >> 5;
                float s = 0.f;
                #pragma unroll
                for (int k = 0; k < 8; k++) s += sred[(q * 8 + k) * CHUNK + c];
                s1[q * CHUNK + c] = s;
            }
            __syncthreads();
            if (t < CHUNK) {
                float s = s1[t] + s1[32 + t] + s1[64 + t] + s1[96 + t]
                        + nrow[i] * hnew[t];
                bcast_f32(&xpar[nxt * D_ + rank * CHUNK + t], s);
            }
            __syncthreads();
            if (t == 0) mbar_arrive_all(barA);
            if (t < IOU_ROWS)
                pre = g_pre_iou[((size_t)b * N_ + i + 1) * (2 * D_) + rank * IOU_ROWS + t];
            if (t < COU_ROWS)
                pre2 = g_pre_cou[((size_t)b * N_ + i + 1) * D_ + rank * COU_ROWS + t];
            if (i + 2 < N_ && t < 128)
                *(float4*)&row_sm[cur * N_ + t * 4] =
                    *(const float4*)&g_normT[((size_t)b * N_ + i + 2) * N_ + t * 4];
            mbar_wait(barA, pA); pA ^= 1;   // x_par_{i+1} visible cluster-wide
        }
    }
}

extern "C" void kernel_launch(void* const* d_in, const int* in_sizes, int n_in,
                              void* d_out, int out_size) {
    const float* h_e    = (const float*)d_in[0];
    const float* adj    = (const float*)d_in[1];
    const float* W_ioux = (const float*)d_in[2];
    const float* b_ioux = (const float*)d_in[3];
    const float* W_iouh = (const float*)d_in[4];
    const float* b_iouh = (const float*)d_in[5];
    const float* W_coux = (const float*)d_in[6];
    const float* b_coux = (const float*)d_in[7];
    const float* W_couh = (const float*)d_in[8];
    const float* b_couh = (const float*)d_in[9];
    float* out = (float*)d_out;

    k_dinv<<<B_ * N_, 256>>>(adj);
    {
        dim3 grid(N_ / 32, N_ / 32, B_), blk(32, 8);
        k_transpose<<<grid, blk>>>(adj);
    }
    {
        dim3 grid(6, (B_ * N_) / 128);   // blocks 0-3: iou, 4-5: cou
        k_gemm_fused<<<grid, 256>>>(h_e, W_ioux, b_ioux, b_iouh,
                                    W_coux, b_coux, b_couh);
    }
    static bool attr_set = false;
    if (!attr_set) {
        cudaFuncSetAttribute(k_main, cudaFuncAttributeMaxDynamicSharedMemorySize,
                             SMEM_BYTES);
        attr_set = true;
    }
    k_main<<<B_ * CLUSTER, MTHREADS, SMEM_BYTES>>>(h_e, W_iouh, W_couh, out);
}

// round 13
// speedup vs baseline: 2.2187x; 2.2187x over previous
#include <cuda_runtime.h>
#include <cuda_fp16.h>
#include <math.h>
#include <stdint.h>

constexpr int B_ = 8;
constexpr int N_ = 512;
constexpr int D_ = 256;

constexpr int CLUSTER  = 8;
constexpr int CHUNK    = 32;   // D/CLUSTER
constexpr int IOU_ROWS = 64;   // 2D/CLUSTER
constexpr int COU_ROWS = 32;   // D/CLUSTER
constexpr int MTHREADS = 256;

// ---- device scratch ----
__device__ __align__(128) float g_dinv[B_ * N_];
__device__ __align__(128) float g_normT[B_ * N_ * N_];
__device__ __align__(128) float g_pre_iou[B_ * N_ * 2 * D_];
__device__ __align__(128) float g_pre_cou[B_ * N_ * D_];

__device__ __forceinline__ float fast_tanh(float x) {
    float r;
    asm("tanh.approx.f32 %0, %1;" : "=f"(r) : "f"(x));
    return r;
}
__device__ __forceinline__ float fast_sigmoid(float x) {
    return 0.5f + 0.5f * fast_tanh(0.5f * x);
}

// ---------------- dinv ----------------
__global__ void k_dinv(const float* __restrict__ adj) {
    int bi = blockIdx.x;
    const float* row = adj + (size_t)bi * N_;
    float s = 0.f;
    for (int j = threadIdx.x; j < N_; j += blockDim.x) s += row[j];
    __shared__ float sm[8];
    #pragma unroll
    for (int o = 16; o; o >>= 1) s += __shfl_down_sync(~0u, s, o);
    if ((threadIdx.x & 31) == 0) sm[threadIdx.x >> 5] = s;
    __syncthreads();
    if (threadIdx.x == 0) {
        float v = 0.f;
        for (int w = 0; w < 8; w++) v += sm[w];
        g_dinv[bi] = (v != 0.f) ? (1.f / v) : 0.f;
    }
}

// ---------------- normT[b][i][j] = adj[b][j][i] * dinv[b][i] ----------------
__global__ void k_transpose(const float* __restrict__ adj) {
    __shared__ float tile[32][33];
    int b = blockIdx.z;
    int i0 = blockIdx.x * 32, j0 = blockIdx.y * 32;
    int tx = threadIdx.x, ty = threadIdx.y;
    const float* A = adj + (size_t)b * N_ * N_;
    #pragma unroll
    for (int q = 0; q < 32; q += 8)
        tile[ty + q][tx] = A[(size_t)(j0 + ty + q) * N_ + i0 + tx];
    __syncthreads();
    float* T = g_normT + (size_t)b * N_ * N_;
    #pragma unroll
    for (int q = 0; q < 32; q += 8) {
        int i = i0 + ty + q;
        T[(size_t)i * N_ + j0 + tx] = tile[tx][ty + q] * g_dinv[b * N_ + i];
    }
}

// -------- fused pre GEMM: blocks 0-3 -> iou tile (P=512), 4-5 -> cou tile (P=256)
__global__ void k_gemm_fused(const float* __restrict__ X,
                             const float* __restrict__ Wi,
                             const float* __restrict__ bi1,
                             const float* __restrict__ bi2,
                             const float* __restrict__ Wc,
                             const float* __restrict__ bc1,
                             const float* __restrict__ bc2) {
    constexpr int BM = 128, BP = 128, BK = 16;
    __shared__ float As[BK][BM];
    __shared__ float Bs[BK][BP];

    const bool is_iou = (blockIdx.x < 4);
    const float* W  = is_iou ? Wi : Wc;
    const float* b1 = is_iou ? bi1 : bc1;
    const float* b2 = is_iou ? bi2 : bc2;
    float* C        = is_iou ? g_pre_iou : g_pre_cou;
    const int P     = is_iou ? 2 * D_ : D_;
    const int p0    = (is_iou ? blockIdx.x : blockIdx.x - 4) * BP;
    const int m0    = blockIdx.y * BM;

    int t = threadIdx.x;
    int tx = t % 16, ty = t / 16;
    float acc[8][8] = {};
    int lrow = t >> 2, lkv = (t & 3) * 4;

    for (int k0 = 0; k0 < D_; k0 += BK) {
        #pragma unroll
        for (int r = 0; r < BM; r += 64) {
            float4 v = *(const float4*)&X[(size_t)(m0 + lrow + r) * D_ + k0 + lkv];
            As[lkv + 0][lrow + r] = v.x; As[lkv + 1][lrow + r] = v.y;
            As[lkv + 2][lrow + r] = v.z; As[lkv + 3][lrow + r] = v.w;
        }
        #pragma unroll
        for (int r = 0; r < BP; r += 64) {
            float4 v = *(const float4*)&W[(size_t)(p0 + lrow + r) * D_ + k0 + lkv];
            Bs[lkv + 0][lrow + r] = v.x; Bs[lkv + 1][lrow + r] = v.y;
            Bs[lkv + 2][lrow + r] = v.z; Bs[lkv + 3][lrow + r] = v.w;
        }
        __syncthreads();
        #pragma unroll
        for (int k = 0; k < BK; k++) {
            float a[8], bb[8];
            *(float4*)&a[0]  = *(const float4*)&As[k][ty * 8];
            *(float4*)&a[4]  = *(const float4*)&As[k][ty * 8 + 4];
            *(float4*)&bb[0] = *(const float4*)&Bs[k][tx * 8];
            *(float4*)&bb[4] = *(const float4*)&Bs[k][tx * 8 + 4];
            #pragma unroll
            for (int im = 0; im < 8; im++)
                #pragma unroll
                for (int ip = 0; ip < 8; ip++)
                    acc[im][ip] += a[im] * bb[ip];
        }
        __syncthreads();
    }
    int pbase = p0 + tx * 8;
    float bs[8];
    #pragma unroll
    for (int ip = 0; ip < 8; ip++) bs[ip] = b1[pbase + ip] + b2[pbase + ip];
    #pragma unroll
    for (int im = 0; im < 8; im++) {
        size_t off = (size_t)(m0 + ty * 8 + im) * P + pbase;
        #pragma unroll
        for (int ip = 0; ip < 8; ip++) C[off + ip] = acc[im][ip] + bs[ip];
    }
}

// ---------------- main sequential cluster kernel (cluster = 8) ----------------
// SMEM byte offsets
constexpr int H_OFF    = 0;                  // float[512*32]   65536
constexpr int ROW_OFF  = 65536;              // float[2*512]     4096
constexpr int XPAR_OFF = 69632;              // float[2*256]     2048
constexpr int V_OFF    = 71680;              // float[256]       1024
constexpr int Z_OFF    = 72704;              // float[256]       1024
constexpr int RED_OFF  = 73728;              // float[512]       2048
constexpr int SRED_OFF = 75776;              // float[1024]      4096
constexpr int S1_OFF   = 79872;              // float[128]        512
constexpr int HNEW_OFF = 80384;              // float[32]         128
constexpr int WIOU_OFF = 80512;              // half[256*64]    32768
constexpr int WCOU_OFF = 113280;             // half[256*32]    16384
constexpr int SMEM_BYTES = 129664;

__device__ __forceinline__ void cluster_arrive() {
    asm volatile("barrier.cluster.arrive.aligned;" ::: "memory");
}
__device__ __forceinline__ void cluster_wait() {
    asm volatile("barrier.cluster.wait.aligned;" ::: "memory");
}
__device__ __forceinline__ void bcast_f32(float* localp, float val) {
    uint32_t l = (uint32_t)__cvta_generic_to_shared(localp);
    uint32_t bits = __float_as_uint(val);
    #pragma unroll
    for (int dst = 0; dst < CLUSTER; dst++) {
        uint32_t r;
        asm("mapa.shared::cluster.u32 %0, %1, %2;" : "=r"(r) : "r"(l), "r"(dst));
        asm volatile("st.shared::cluster.u32 [%0], %1;" :: "r"(r), "r"(bits));
    }
}

extern __shared__ char smem_raw[];

__global__ void __cluster_dims__(CLUSTER, 1, 1) __launch_bounds__(MTHREADS, 1)
k_main(const float* __restrict__ h_e,
       const float* __restrict__ W_iouh,
       const float* __restrict__ W_couh,
       float* __restrict__ out) {
    float* h_sm   = (float*)(smem_raw + H_OFF);     // [512][32]
    float* row_sm = (float*)(smem_raw + ROW_OFF);   // [2][512]
    float* xpar   = (float*)(smem_raw + XPAR_OFF);  // [2][256]
    float* vbuf   = (float*)(smem_raw + V_OFF);
    float* zbuf   = (float*)(smem_raw + Z_OFF);
    float* red    = (float*)(smem_raw + RED_OFF);   // [512]
    float* sred   = (float*)(smem_raw + SRED_OFF);  // [32][32]
    float* s1     = (float*)(smem_raw + S1_OFF);    // [4][32]
    float* hnew   = (float*)(smem_raw + HNEW_OFF);  // [32]
    __half* wiou  = (__half*)(smem_raw + WIOU_OFF); // [256][64] d-major
    __half* wcou  = (__half*)(smem_raw + WCOU_OFF); // [256][32] d-major
    const __half2* wiou2 = (const __half2*)wiou;
    const __half2* wcou2 = (const __half2*)wcou;

    const int t = threadIdx.x;
    const int rank = blockIdx.x % CLUSTER;
    const int b = blockIdx.x / CLUSTER;

    // skip-one aggregation into sred
    auto sgemv = [&](const float* rowp, int skip) {
        int c4 = (t & 7) * 4, g = t >> 3;
        float4 acc = make_float4(0.f, 0.f, 0.f, 0.f);
        #pragma unroll
        for (int jj = 0; jj < 16; jj++) {
            int r = g + 32 * jj;
            if (r != skip) {
                float rv = rowp[r];
                float4 hv = *(const float4*)&h_sm[r * CHUNK + c4];
                acc.x += rv * hv.x; acc.y += rv * hv.y;
                acc.z += rv * hv.z; acc.w += rv * hv.w;
            }
        }
        *(float4*)&sred[g * CHUNK + c4] = acc;
    };

    // ---- init: h chunk, fp16 weight slices, rows 0/1 ----
    {
        const float* src = h_e + (size_t)b * N_ * D_ + rank * CHUNK;
        for (int idx = t; idx < N_ * CHUNK; idx += MTHREADS) {
            int j = idx / CHUNK, c = idx % CHUNK;
            h_sm[j * CHUNK + c] = src[(size_t)j * D_ + c];
        }
        const float* ws = W_iouh + (size_t)(rank * IOU_ROWS) * D_;
        for (int idx = t; idx < IOU_ROWS * D_; idx += MTHREADS) {
            int p = idx / D_, d = idx % D_;
            wiou[d * IOU_ROWS + p] = __float2half(ws[idx]);
        }
        const float* wc = W_couh + (size_t)(rank * COU_ROWS) * D_;
        for (int idx = t; idx < COU_ROWS * D_; idx += MTHREADS) {
            int p = idx / D_, d = idx % D_;
            wcou[d * COU_ROWS + p] = __float2half(wc[idx]);
        }
        if (t < 128) {
            *(float4*)&row_sm[t * 4] =
                *(const float4*)&g_normT[((size_t)b * N_) * N_ + t * 4];
            *(float4*)&row_sm[512 + t * 4] =
                *(const float4*)&g_normT[((size_t)b * N_ + 1) * N_ + t * 4];
        }
    }
    __syncthreads();

    float pre = 0.f, pre2 = 0.f;

    // ---- bootstrap: x_par_0 ----
    sgemv(&row_sm[0], -1);
    __syncthreads();
    if (t < 128) {
        int c = t & 31, q = t >> 5;
        float s = 0.f;
        #pragma unroll
        for (int k = 0; k < 8; k++) s += sred[(q * 8 + k) * CHUNK + c];
        s1[q * CHUNK + c] = s;
    }
    __syncthreads();
    if (t < CHUNK) {
        float s = s1[t] + s1[32 + t] + s1[64 + t] + s1[96 + t];
        bcast_f32(&xpar[rank * CHUNK + t], s);
    }
    cluster_arrive();
    if (t < IOU_ROWS)
        pre = g_pre_iou[((size_t)b * N_) * (2 * D_) + rank * IOU_ROWS + t];
    if (t < COU_ROWS)
        pre2 = g_pre_cou[((size_t)b * N_) * D_ + rank * COU_ROWS + t];
    cluster_wait();

    for (int i = 0; i < N_; i++) {
        const int cur = i & 1;
        const int nxt = cur ^ 1;
        const float* xp_cur = &xpar[cur * D_];
        const float* nrow = &row_sm[nxt * N_];  // row_{i+1}

        // ---- phase 2: iou GEMV (fp16 weights, fp32 acc) ----
        {
            int pp = t & 31, q = t >> 5;  // 8 d-groups of 32
            float a0 = 0.f, a1 = 0.f;
            const float* xp = xp_cur + q * 32;
            #pragma unroll
            for (int dd = 0; dd < 32; dd++) {
                float xv = xp[dd];
                float2 wf = __half22float2(wiou2[(q * 32 + dd) * 32 + pp]);
                a0 += xv * wf.x; a1 += xv * wf.y;
            }
            red[q * IOU_ROWS + 2 * pp]     = a0;
            red[q * IOU_ROWS + 2 * pp + 1] = a1;
        }
        __syncthreads();
        if (t < IOU_ROWS) {
            float s = pre;
            #pragma unroll
            for (int q = 0; q < 8; q++) s += red[q * IOU_ROWS + t];
            float sg = fast_sigmoid(s);
            if (rank < 4) {
                int gp = rank * IOU_ROWS + t;
                bcast_f32(&vbuf[gp], xp_cur[gp] * sg);
            } else {
                bcast_f32(&zbuf[(rank - 4) * IOU_ROWS + t], sg);
            }
        }
        cluster_arrive();
        // hide the big aggregation for x_par_{i+1} behind barrier 2
        if (i + 1 < N_) sgemv(nrow, i);
        cluster_wait();  // v, z visible cluster-wide

        // ---- phase 3: couh GEMV + tanh + update ----
        {
            int pp = t & 15, q = t >> 4;  // 16 d-groups of 16
            float a0 = 0.f, a1 = 0.f;
            const float* vp = &vbuf[q * 16];
            #pragma unroll
            for (int dd = 0; dd < 16; dd++) {
                float vv = vp[dd];
                float2 wf = __half22float2(wcou2[(q * 16 + dd) * 16 + pp]);
                a0 += vv * wf.x; a1 += vv * wf.y;
            }
            red[q * COU_ROWS + 2 * pp]     = a0;
            red[q * COU_ROWS + 2 * pp + 1] = a1;
        }
        __syncthreads();
        if (t < COU_ROWS) {
            float s = pre2;
            #pragma unroll
            for (int q = 0; q < 16; q++) s += red[q * COU_ROWS + t];
            float hc  = fast_tanh(s);
            float xpv = xp_cur[rank * COU_ROWS + t];
            float zz  = zbuf[rank * COU_ROWS + t];
            float hn  = zz * xpv + (1.f - zz) * hc;
            h_sm[i * CHUNK + t] = hn;
            hnew[t] = hn;
            out[((size_t)b * N_ + i) * D_ + rank * COU_ROWS + t] = hn;
        }
        __syncthreads();  // hnew + sred stores visible

        if (i + 1 < N_) {
            if (t < 128) {
                int c = t & 31, q = t >> 5;
                float s = 0.f;
                #pragma unroll
                for (int k = 0; k < 8; k++) s += sred[(q * 8 + k) * CHUNK + c];
                s1[q * CHUNK + c] = s;
            }
            __syncthreads();
            if (t < CHUNK) {
                float s = s1[t] + s1[32 + t] + s1[64 + t] + s1[96 + t]
                        + nrow[i] * hnew[t];
                bcast_f32(&xpar[nxt * D_ + rank * CHUNK + t], s);
            }
            cluster_arrive();
            if (t < IOU_ROWS)
                pre = g_pre_iou[((size_t)b * N_ + i + 1) * (2 * D_) + rank * IOU_ROWS + t];
            if (t < COU_ROWS)
                pre2 = g_pre_cou[((size_t)b * N_ + i + 1) * D_ + rank * COU_ROWS + t];
            if (i + 2 < N_ && t < 128)
                *(float4*)&row_sm[cur * N_ + t * 4] =
                    *(const float4*)&g_normT[((size_t)b * N_ + i + 2) * N_ + t * 4];
            cluster_wait();  // x_par_{i+1} visible cluster-wide
        }
    }
}

extern "C" void kernel_launch(void* const* d_in, const int* in_sizes, int n_in,
                              void* d_out, int out_size) {
    const float* h_e    = (const float*)d_in[0];
    const float* adj    = (const float*)d_in[1];
    const float* W_ioux = (const float*)d_in[2];
    const float* b_ioux = (const float*)d_in[3];
    const float* W_iouh = (const float*)d_in[4];
    const float* b_iouh = (const float*)d_in[5];
    const float* W_coux = (const float*)d_in[6];
    const float* b_coux = (const float*)d_in[7];
    const float* W_couh = (const float*)d_in[8];
    const float* b_couh = (const float*)d_in[9];
    float* out = (float*)d_out;

    static cudaStream_t s2 = nullptr;
    static cudaEvent_t ev_fork = nullptr, ev_join = nullptr;
    static bool init_done = false;
    if (!init_done) {
        cudaStreamCreateWithFlags(&s2, cudaStreamNonBlocking);
        cudaEventCreateWithFlags(&ev_fork, cudaEventDisableTiming);
        cudaEventCreateWithFlags(&ev_join, cudaEventDisableTiming);
        cudaFuncSetAttribute(k_main, cudaFuncAttributeMaxDynamicSharedMemorySize,
                             SMEM_BYTES);
        init_done = true;
    }

    // fork: pre-GEMM on s2 runs concurrently with dinv+transpose on stream 0
    cudaEventRecord(ev_fork, 0);
    cudaStreamWaitEvent(s2, ev_fork, 0);
    {
        dim3 grid(6, (B_ * N_) / 128);   // blocks 0-3: iou, 4-5: cou
        k_gemm_fused<<<grid, 256, 0, s2>>>(h_e, W_ioux, b_ioux, b_iouh,
                                           W_coux, b_coux, b_couh);
    }
    k_dinv<<<B_ * N_, 256>>>(adj);
    {
        dim3 grid(N_ / 32, N_ / 32, B_), blk(32, 8);
        k_transpose<<<grid, blk>>>(adj);
    }
    // join
    cudaEventRecord(ev_join, s2);
    cudaStreamWaitEvent(0, ev_join, 0);

    k_main<<<B_ * CLUSTER, MTHREADS, SMEM_BYTES>>>(h_e, W_iouh, W_couh, out);
}

// round 14
// speedup vs baseline: 2.2443x; 1.0116x over previous
#include <cuda_runtime.h>
#include <cuda_fp16.h>
#include <math.h>
#include <stdint.h>

constexpr int B_ = 8;
constexpr int N_ = 512;
constexpr int D_ = 256;

constexpr int CLUSTER  = 8;
constexpr int CHUNK    = 32;   // D/CLUSTER
constexpr int IOU_ROWS = 64;   // 2D/CLUSTER
constexpr int COU_ROWS = 32;   // D/CLUSTER
constexpr int MTHREADS = 256;

// ---- device scratch ----
__device__ __align__(128) float g_dinv[B_ * N_];
__device__ __align__(128) float g_normT[B_ * N_ * N_];
__device__ __align__(128) float g_pre_iou[B_ * N_ * 2 * D_];
__device__ __align__(128) float g_pre_cou[B_ * N_ * D_];

__device__ __forceinline__ float fast_tanh(float x) {
    float r;
    asm("tanh.approx.f32 %0, %1;" : "=f"(r) : "f"(x));
    return r;
}
__device__ __forceinline__ float fast_sigmoid(float x) {
    return 0.5f + 0.5f * fast_tanh(0.5f * x);
}

// ---------------- dinv ----------------
__global__ void k_dinv(const float* __restrict__ adj) {
    int bi = blockIdx.x;
    const float* row = adj + (size_t)bi * N_;
    float s = 0.f;
    for (int j = threadIdx.x; j < N_; j += blockDim.x) s += row[j];
    __shared__ float sm[8];
    #pragma unroll
    for (int o = 16; o; o >>= 1) s += __shfl_down_sync(~0u, s, o);
    if ((threadIdx.x & 31) == 0) sm[threadIdx.x >> 5] = s;
    __syncthreads();
    if (threadIdx.x == 0) {
        float v = 0.f;
        for (int w = 0; w < 8; w++) v += sm[w];
        g_dinv[bi] = (v != 0.f) ? (1.f / v) : 0.f;
    }
}

// ---------------- normT[b][i][j] = adj[b][j][i] * dinv[b][i] ----------------
__global__ void k_transpose(const float* __restrict__ adj) {
    __shared__ float tile[32][33];
    int b = blockIdx.z;
    int i0 = blockIdx.x * 32, j0 = blockIdx.y * 32;
    int tx = threadIdx.x, ty = threadIdx.y;
    const float* A = adj + (size_t)b * N_ * N_;
    #pragma unroll
    for (int q = 0; q < 32; q += 8)
        tile[ty + q][tx] = A[(size_t)(j0 + ty + q) * N_ + i0 + tx];
    __syncthreads();
    float* T = g_normT + (size_t)b * N_ * N_;
    #pragma unroll
    for (int q = 0; q < 32; q += 8) {
        int i = i0 + ty + q;
        T[(size_t)i * N_ + j0 + tx] = tile[tx][ty + q] * g_dinv[b * N_ + i];
    }
}

// -------- fused pre GEMM: blocks 0-3 -> iou tile (P=512), 4-5 -> cou tile (P=256)
__global__ void k_gemm_fused(const float* __restrict__ X,
                             const float* __restrict__ Wi,
                             const float* __restrict__ bi1,
                             const float* __restrict__ bi2,
                             const float* __restrict__ Wc,
                             const float* __restrict__ bc1,
                             const float* __restrict__ bc2) {
    constexpr int BM = 128, BP = 128, BK = 16;
    __shared__ float As[BK][BM];
    __shared__ float Bs[BK][BP];

    const bool is_iou = (blockIdx.x < 4);
    const float* W  = is_iou ? Wi : Wc;
    const float* b1 = is_iou ? bi1 : bc1;
    const float* b2 = is_iou ? bi2 : bc2;
    float* C        = is_iou ? g_pre_iou : g_pre_cou;
    const int P     = is_iou ? 2 * D_ : D_;
    const int p0    = (is_iou ? blockIdx.x : blockIdx.x - 4) * BP;
    const int m0    = blockIdx.y * BM;

    int t = threadIdx.x;
    int tx = t % 16, ty = t / 16;
    float acc[8][8] = {};
    int lrow = t >> 2, lkv = (t & 3) * 4;

    for (int k0 = 0; k0 < D_; k0 += BK) {
        #pragma unroll
        for (int r = 0; r < BM; r += 64) {
            float4 v = *(const float4*)&X[(size_t)(m0 + lrow + r) * D_ + k0 + lkv];
            As[lkv + 0][lrow + r] = v.x; As[lkv + 1][lrow + r] = v.y;
            As[lkv + 2][lrow + r] = v.z; As[lkv + 3][lrow + r] = v.w;
        }
        #pragma unroll
        for (int r = 0; r < BP; r += 64) {
            float4 v = *(const float4*)&W[(size_t)(p0 + lrow + r) * D_ + k0 + lkv];
            Bs[lkv + 0][lrow + r] = v.x; Bs[lkv + 1][lrow + r] = v.y;
            Bs[lkv + 2][lrow + r] = v.z; Bs[lkv + 3][lrow + r] = v.w;
        }
        __syncthreads();
        #pragma unroll
        for (int k = 0; k < BK; k++) {
            float a[8], bb[8];
            *(float4*)&a[0]  = *(const float4*)&As[k][ty * 8];
            *(float4*)&a[4]  = *(const float4*)&As[k][ty * 8 + 4];
            *(float4*)&bb[0] = *(const float4*)&Bs[k][tx * 8];
            *(float4*)&bb[4] = *(const float4*)&Bs[k][tx * 8 + 4];
            #pragma unroll
            for (int im = 0; im < 8; im++)
                #pragma unroll
                for (int ip = 0; ip < 8; ip++)
                    acc[im][ip] += a[im] * bb[ip];
        }
        __syncthreads();
    }
    int pbase = p0 + tx * 8;
    float bs[8];
    #pragma unroll
    for (int ip = 0; ip < 8; ip++) bs[ip] = b1[pbase + ip] + b2[pbase + ip];
    #pragma unroll
    for (int im = 0; im < 8; im++) {
        size_t off = (size_t)(m0 + ty * 8 + im) * P + pbase;
        #pragma unroll
        for (int ip = 0; ip < 8; ip++) C[off + ip] = acc[im][ip] + bs[ip];
    }
}

// ---------------- main sequential cluster kernel (cluster = 8) ----------------
// SMEM byte offsets
constexpr int H_OFF    = 0;                  // float[512*32]   65536
constexpr int ROW_OFF  = 65536;              // float[2*512]     4096
constexpr int XPAR_OFF = 69632;              // float[2*256]     2048
constexpr int V_OFF    = 71680;              // float[256]       1024
constexpr int Z_OFF    = 72704;              // float[256]       1024
constexpr int RED_OFF  = 73728;              // float[512]       2048
constexpr int SRED_OFF = 75776;              // float[1024]      4096
constexpr int S1_OFF   = 79872;              // float[128]        512
constexpr int WIOU_OFF = 80512;              // half[256*64]    32768
constexpr int WCOU_OFF = 113280;             // half[256*32]    16384
constexpr int SMEM_BYTES = 129664;

__device__ __forceinline__ void cluster_arrive() {
    asm volatile("barrier.cluster.arrive.aligned;" ::: "memory");
}
__device__ __forceinline__ void cluster_wait() {
    asm volatile("barrier.cluster.wait.aligned;" ::: "memory");
}
__device__ __forceinline__ void bcast_f32(float* localp, float val) {
    uint32_t l = (uint32_t)__cvta_generic_to_shared(localp);
    uint32_t bits = __float_as_uint(val);
    #pragma unroll
    for (int dst = 0; dst < CLUSTER; dst++) {
        uint32_t r;
        asm("mapa.shared::cluster.u32 %0, %1, %2;" : "=r"(r) : "r"(l), "r"(dst));
        asm volatile("st.shared::cluster.u32 [%0], %1;" :: "r"(r), "r"(bits));
    }
}

extern __shared__ char smem_raw[];

__global__ void __cluster_dims__(CLUSTER, 1, 1) __launch_bounds__(MTHREADS, 1)
k_main(const float* __restrict__ h_e,
       const float* __restrict__ W_iouh,
       const float* __restrict__ W_couh,
       float* __restrict__ out) {
    float* h_sm   = (float*)(smem_raw + H_OFF);     // [512][32]
    float* row_sm = (float*)(smem_raw + ROW_OFF);   // [2][512]
    float* xpar   = (float*)(smem_raw + XPAR_OFF);  // [2][256]
    float* vbuf   = (float*)(smem_raw + V_OFF);
    float* zbuf   = (float*)(smem_raw + Z_OFF);
    float* red    = (float*)(smem_raw + RED_OFF);   // [512]
    float* sred   = (float*)(smem_raw + SRED_OFF);  // [32][32]
    float* s1     = (float*)(smem_raw + S1_OFF);    // [4][32]
    __half* wiou  = (__half*)(smem_raw + WIOU_OFF); // [256][64] d-major
    __half* wcou  = (__half*)(smem_raw + WCOU_OFF); // [256][32] d-major
    const __half2* wiou2 = (const __half2*)wiou;
    const __half2* wcou2 = (const __half2*)wcou;

    const int t = threadIdx.x;
    const int rank = blockIdx.x % CLUSTER;
    const int b = blockIdx.x / CLUSTER;

    // skip-one aggregation into sred
    auto sgemv = [&](const float* rowp, int skip) {
        int c4 = (t & 7) * 4, g = t >> 3;
        float4 acc = make_float4(0.f, 0.f, 0.f, 0.f);
        #pragma unroll
        for (int jj = 0; jj < 16; jj++) {
            int r = g + 32 * jj;
            if (r != skip) {
                float rv = rowp[r];
                float4 hv = *(const float4*)&h_sm[r * CHUNK + c4];
                acc.x += rv * hv.x; acc.y += rv * hv.y;
                acc.z += rv * hv.z; acc.w += rv * hv.w;
            }
        }
        *(float4*)&sred[g * CHUNK + c4] = acc;
    };

    // ---- init: h chunk, fp16 weight slices, rows 0/1 ----
    {
        const float* src = h_e + (size_t)b * N_ * D_ + rank * CHUNK;
        for (int idx = t; idx < N_ * CHUNK; idx += MTHREADS) {
            int j = idx / CHUNK, c = idx % CHUNK;
            h_sm[j * CHUNK + c] = src[(size_t)j * D_ + c];
        }
        const float* ws = W_iouh + (size_t)(rank * IOU_ROWS) * D_;
        for (int idx = t; idx < IOU_ROWS * D_; idx += MTHREADS) {
            int p = idx / D_, d = idx % D_;
            wiou[d * IOU_ROWS + p] = __float2half(ws[idx]);
        }
        const float* wc = W_couh + (size_t)(rank * COU_ROWS) * D_;
        for (int idx = t; idx < COU_ROWS * D_; idx += MTHREADS) {
            int p = idx / D_, d = idx % D_;
            wcou[d * COU_ROWS + p] = __float2half(wc[idx]);
        }
        if (t < 128) {
            *(float4*)&row_sm[t * 4] =
                *(const float4*)&g_normT[((size_t)b * N_) * N_ + t * 4];
            *(float4*)&row_sm[512 + t * 4] =
                *(const float4*)&g_normT[((size_t)b * N_ + 1) * N_ + t * 4];
        }
    }
    __syncthreads();

    float pre = 0.f, pre2 = 0.f;

    // ---- bootstrap: x_par_0 ----
    sgemv(&row_sm[0], -1);
    __syncthreads();
    if (t < 128) {
        int c = t & 31, q = t >> 5;
        float s = 0.f;
        #pragma unroll
        for (int k = 0; k < 8; k++) s += sred[(q * 8 + k) * CHUNK + c];
        s1[q * CHUNK + c] = s;
    }
    __syncthreads();
    if (t < CHUNK) {
        float s = s1[t] + s1[32 + t] + s1[64 + t] + s1[96 + t];
        bcast_f32(&xpar[rank * CHUNK + t], s);
    }
    cluster_arrive();
    if (t < IOU_ROWS)
        pre = g_pre_iou[((size_t)b * N_) * (2 * D_) + rank * IOU_ROWS + t];
    if (t < COU_ROWS)
        pre2 = g_pre_cou[((size_t)b * N_) * D_ + rank * COU_ROWS + t];
    cluster_wait();

    for (int i = 0; i < N_; i++) {
        const int cur = i & 1;
        const int nxt = cur ^ 1;
        const float* xp_cur = &xpar[cur * D_];
        const float* nrow = &row_sm[nxt * N_];  // row_{i+1}

        // ---- phase 2: iou GEMV (fp16 weights, fp32 acc) ----
        {
            int pp = t & 31, q = t >> 5;  // 8 d-groups of 32
            float a0 = 0.f, a1 = 0.f;
            const float* xp = xp_cur + q * 32;
            #pragma unroll
            for (int dd = 0; dd < 32; dd++) {
                float xv = xp[dd];
                float2 wf = __half22float2(wiou2[(q * 32 + dd) * 32 + pp]);
                a0 += xv * wf.x; a1 += xv * wf.y;
            }
            *(float2*)&red[q * IOU_ROWS + 2 * pp] = make_float2(a0, a1);
        }
        __syncthreads();
        if (t < IOU_ROWS) {
            float s = pre;
            #pragma unroll
            for (int q = 0; q < 8; q++) s += red[q * IOU_ROWS + t];
            float sg = fast_sigmoid(s);
            if (rank < 4) {
                int gp = rank * IOU_ROWS + t;
                bcast_f32(&vbuf[gp], xp_cur[gp] * sg);
            } else {
                bcast_f32(&zbuf[(rank - 4) * IOU_ROWS + t], sg);
            }
        }
        cluster_arrive();
        // hide the big aggregation for x_par_{i+1} behind barrier 2
        if (i + 1 < N_) sgemv(nrow, i);
        cluster_wait();  // v, z visible cluster-wide
        __syncthreads();  // sred (gap writes) visible CTA-wide

        // ---- phase 3 GEMV (t<128, 8 d-groups of 32) ∥ s1 sred-reduce (t>=128) ----
        if (t < 128) {
            int pp = t & 15, q = t >> 4;
            float a0 = 0.f, a1 = 0.f;
            const float* vp = &vbuf[q * 32];
            #pragma unroll
            for (int d4 = 0; d4 < 8; d4++) {
                float4 vv = *(const float4*)&vp[d4 * 4];
                #pragma unroll
                for (int k = 0; k < 4; k++) {
                    float vs = (&vv.x)[k];
                    float2 wf = __half22float2(wcou2[(q * 32 + d4 * 4 + k) * 16 + pp]);
                    a0 += vs * wf.x; a1 += vs * wf.y;
                }
            }
            *(float2*)&red[q * COU_ROWS + 2 * pp] = make_float2(a0, a1);
        } else {
            int tt = t - 128;
            int c = tt & 31, q = tt >> 5;
            float s = 0.f;
            #pragma unroll
            for (int k = 0; k < 8; k++) s += sred[(q * 8 + k) * CHUNK + c];
            s1[q * CHUNK + c] = s;
        }
        __syncthreads();

        // ---- fused finish: cou sum + tanh + h update + xpar_{i+1} bcast ----
        if (t < COU_ROWS) {
            float s = pre2;
            #pragma unroll
            for (int q = 0; q < 8; q++) s += red[q * COU_ROWS + t];
            float hc  = fast_tanh(s);
            float xpv = xp_cur[rank * COU_ROWS + t];
            float zz  = zbuf[rank * COU_ROWS + t];
            float hn  = zz * xpv + (1.f - zz) * hc;
            h_sm[i * CHUNK + t] = hn;
            out[((size_t)b * N_ + i) * D_ + rank * COU_ROWS + t] = hn;
            if (i + 1 < N_) {
                float sx = s1[t] + s1[32 + t] + s1[64 + t] + s1[96 + t]
                         + nrow[i] * hn;
                bcast_f32(&xpar[nxt * D_ + rank * CHUNK + t], sx);
            }
        }

        if (i + 1 < N_) {
            cluster_arrive();
            if (t < IOU_ROWS)
                pre = g_pre_iou[((size_t)b * N_ + i + 1) * (2 * D_) + rank * IOU_ROWS + t];
            if (t < COU_ROWS)
                pre2 = g_pre_cou[((size_t)b * N_ + i + 1) * D_ + rank * COU_ROWS + t];
            if (i + 2 < N_ && t < 128)
                *(float4*)&row_sm[cur * N_ + t * 4] =
                    *(const float4*)&g_normT[((size_t)b * N_ + i + 2) * N_ + t * 4];
            cluster_wait();  // x_par_{i+1} (and h row i) visible cluster-wide
        }
    }
}

extern "C" void kernel_launch(void* const* d_in, const int* in_sizes, int n_in,
                              void* d_out, int out_size) {
    const float* h_e    = (const float*)d_in[0];
    const float* adj    = (const float*)d_in[1];
    const float* W_ioux = (const float*)d_in[2];
    const float* b_ioux = (const float*)d_in[3];
    const float* W_iouh = (const float*)d_in[4];
    const float* b_iouh = (const float*)d_in[5];
    const float* W_coux = (const float*)d_in[6];
    const float* b_coux = (const float*)d_in[7];
    const float* W_couh = (const float*)d_in[8];
    const float* b_couh = (const float*)d_in[9];
    float* out = (float*)d_out;

    static cudaStream_t s2 = nullptr;
    static cudaEvent_t ev_fork = nullptr, ev_join = nullptr;
    static bool init_done = false;
    if (!init_done) {
        cudaStreamCreateWithFlags(&s2, cudaStreamNonBlocking);
        cudaEventCreateWithFlags(&ev_fork, cudaEventDisableTiming);
        cudaEventCreateWithFlags(&ev_join, cudaEventDisableTiming);
        cudaFuncSetAttribute(k_main, cudaFuncAttributeMaxDynamicSharedMemorySize,
                             SMEM_BYTES);
        init_done = true;
    }

    cudaEventRecord(ev_fork, 0);
    cudaStreamWaitEvent(s2, ev_fork, 0);
    {
        dim3 grid(6, (B_ * N_) / 128);   // blocks 0-3: iou, 4-5: cou
        k_gemm_fused<<<grid, 256, 0, s2>>>(h_e, W_ioux, b_ioux, b_iouh,
                                           W_coux, b_coux, b_couh);
    }
    k_dinv<<<B_ * N_, 256>>>(adj);
    {
        dim3 grid(N_ / 32, N_ / 32, B_), blk(32, 8);
        k_transpose<<<grid, blk>>>(adj);
    }
    cudaEventRecord(ev_join, s2);
    cudaStreamWaitEvent(0, ev_join, 0);

    k_main<<<B_ * CLUSTER, MTHREADS, SMEM_BYTES>>>(h_e, W_iouh, W_couh, out);
}

// round 15
// speedup vs baseline: 2.2488x; 1.0020x over previous
#include <cuda_runtime.h>
#include <cuda_fp16.h>
#include <math.h>
#include <stdint.h>

constexpr int B_ = 8;
constexpr int N_ = 512;
constexpr int D_ = 256;

constexpr int CLUSTER  = 8;
constexpr int CHUNK    = 32;   // D/CLUSTER
constexpr int IOU_ROWS = 64;   // 2D/CLUSTER
constexpr int COU_ROWS = 32;   // D/CLUSTER
constexpr int MTHREADS = 256;

// ---- device scratch ----
__device__ __align__(128) float g_dinv[B_ * N_];
__device__ __align__(128) float g_normT[B_ * N_ * N_];
__device__ __align__(128) float g_pre_iou[B_ * N_ * 2 * D_];
__device__ __align__(128) float g_pre_cou[B_ * N_ * D_];

__device__ __forceinline__ float fast_tanh(float x) {
    float r;
    asm("tanh.approx.f32 %0, %1;" : "=f"(r) : "f"(x));
    return r;
}
__device__ __forceinline__ float fast_sigmoid(float x) {
    return 0.5f + 0.5f * fast_tanh(0.5f * x);
}

// ---------------- dinv ----------------
__global__ void k_dinv(const float* __restrict__ adj) {
    int bi = blockIdx.x;
    const float* row = adj + (size_t)bi * N_;
    float s = 0.f;
    for (int j = threadIdx.x; j < N_; j += blockDim.x) s += row[j];
    __shared__ float sm[8];
    #pragma unroll
    for (int o = 16; o; o >>= 1) s += __shfl_down_sync(~0u, s, o);
    if ((threadIdx.x & 31) == 0) sm[threadIdx.x >> 5] = s;
    __syncthreads();
    if (threadIdx.x == 0) {
        float v = 0.f;
        for (int w = 0; w < 8; w++) v += sm[w];
        g_dinv[bi] = (v != 0.f) ? (1.f / v) : 0.f;
    }
}

// ---------------- normT[b][i][j] = adj[b][j][i] * dinv[b][i] ----------------
__global__ void k_transpose(const float* __restrict__ adj) {
    __shared__ float tile[32][33];
    int b = blockIdx.z;
    int i0 = blockIdx.x * 32, j0 = blockIdx.y * 32;
    int tx = threadIdx.x, ty = threadIdx.y;
    const float* A = adj + (size_t)b * N_ * N_;
    #pragma unroll
    for (int q = 0; q < 32; q += 8)
        tile[ty + q][tx] = A[(size_t)(j0 + ty + q) * N_ + i0 + tx];
    __syncthreads();
    float* T = g_normT + (size_t)b * N_ * N_;
    #pragma unroll
    for (int q = 0; q < 32; q += 8) {
        int i = i0 + ty + q;
        T[(size_t)i * N_ + j0 + tx] = tile[tx][ty + q] * g_dinv[b * N_ + i];
    }
}

// -------- fused pre GEMM: blocks 0-3 -> iou tile (P=512), 4-5 -> cou tile (P=256)
__global__ void k_gemm_fused(const float* __restrict__ X,
                             const float* __restrict__ Wi,
                             const float* __restrict__ bi1,
                             const float* __restrict__ bi2,
                             const float* __restrict__ Wc,
                             const float* __restrict__ bc1,
                             const float* __restrict__ bc2) {
    constexpr int BM = 128, BP = 128, BK = 16;
    __shared__ float As[BK][BM];
    __shared__ float Bs[BK][BP];

    const bool is_iou = (blockIdx.x < 4);
    const float* W  = is_iou ? Wi : Wc;
    const float* b1 = is_iou ? bi1 : bc1;
    const float* b2 = is_iou ? bi2 : bc2;
    float* C        = is_iou ? g_pre_iou : g_pre_cou;
    const int P     = is_iou ? 2 * D_ : D_;
    const int p0    = (is_iou ? blockIdx.x : blockIdx.x - 4) * BP;
    const int m0    = blockIdx.y * BM;

    int t = threadIdx.x;
    int tx = t % 16, ty = t / 16;
    float acc[8][8] = {};
    int lrow = t >> 2, lkv = (t & 3) * 4;

    for (int k0 = 0; k0 < D_; k0 += BK) {
        #pragma unroll
        for (int r = 0; r < BM; r += 64) {
            float4 v = *(const float4*)&X[(size_t)(m0 + lrow + r) * D_ + k0 + lkv];
            As[lkv + 0][lrow + r] = v.x; As[lkv + 1][lrow + r] = v.y;
            As[lkv + 2][lrow + r] = v.z; As[lkv + 3][lrow + r] = v.w;
        }
        #pragma unroll
        for (int r = 0; r < BP; r += 64) {
            float4 v = *(const float4*)&W[(size_t)(p0 + lrow + r) * D_ + k0 + lkv];
            Bs[lkv + 0][lrow + r] = v.x; Bs[lkv + 1][lrow + r] = v.y;
            Bs[lkv + 2][lrow + r] = v.z; Bs[lkv + 3][lrow + r] = v.w;
        }
        __syncthreads();
        #pragma unroll
        for (int k = 0; k < BK; k++) {
            float a[8], bb[8];
            *(float4*)&a[0]  = *(const float4*)&As[k][ty * 8];
            *(float4*)&a[4]  = *(const float4*)&As[k][ty * 8 + 4];
            *(float4*)&bb[0] = *(const float4*)&Bs[k][tx * 8];
            *(float4*)&bb[4] = *(const float4*)&Bs[k][tx * 8 + 4];
            #pragma unroll
            for (int im = 0; im < 8; im++)
                #pragma unroll
                for (int ip = 0; ip < 8; ip++)
                    acc[im][ip] += a[im] * bb[ip];
        }
        __syncthreads();
    }
    int pbase = p0 + tx * 8;
    float bs[8];
    #pragma unroll
    for (int ip = 0; ip < 8; ip++) bs[ip] = b1[pbase + ip] + b2[pbase + ip];
    #pragma unroll
    for (int im = 0; im < 8; im++) {
        size_t off = (size_t)(m0 + ty * 8 + im) * P + pbase;
        #pragma unroll
        for (int ip = 0; ip < 8; ip++) C[off + ip] = acc[im][ip] + bs[ip];
    }
}

// ---------------- main sequential cluster kernel (cluster = 8) ----------------
// SMEM byte offsets
constexpr int H_OFF    = 0;                  // float[512*32]   65536
constexpr int ROW_OFF  = 65536;              // float[2*512]     4096
constexpr int XPAR_OFF = 69632;              // float[2*256]     2048
constexpr int V_OFF    = 71680;              // float[256]       1024
constexpr int Z_OFF    = 72704;              // float[256]       1024
constexpr int RED_OFF  = 73728;              // float[512]       2048
constexpr int SRED_OFF = 75776;              // float[1024]      4096
constexpr int S1_OFF   = 79872;              // float[128]        512
constexpr int WIOU_OFF = 80512;              // half[256*64]    32768
constexpr int WCOU_OFF = 113280;             // half[256*32]    16384
constexpr int SMEM_BYTES = 129664;

__device__ __forceinline__ void cluster_arrive() {
    asm volatile("barrier.cluster.arrive.aligned;" ::: "memory");
}
__device__ __forceinline__ void cluster_wait() {
    asm volatile("barrier.cluster.wait.aligned;" ::: "memory");
}
__device__ __forceinline__ void bcast_f32(float* localp, float val) {
    uint32_t l = (uint32_t)__cvta_generic_to_shared(localp);
    uint32_t bits = __float_as_uint(val);
    #pragma unroll
    for (int dst = 0; dst < CLUSTER; dst++) {
        uint32_t r;
        asm("mapa.shared::cluster.u32 %0, %1, %2;" : "=r"(r) : "r"(l), "r"(dst));
        asm volatile("st.shared::cluster.u32 [%0], %1;" :: "r"(r), "r"(bits));
    }
}

extern __shared__ char smem_raw[];

__global__ void __cluster_dims__(CLUSTER, 1, 1) __launch_bounds__(MTHREADS, 1)
k_main(const float* __restrict__ h_e,
       const float* __restrict__ W_iouh,
       const float* __restrict__ W_couh,
       float* __restrict__ out) {
    float* h_sm   = (float*)(smem_raw + H_OFF);     // [512][32]
    float* row_sm = (float*)(smem_raw + ROW_OFF);   // [2][512]
    float* xpar   = (float*)(smem_raw + XPAR_OFF);  // [2][256]
    float* vbuf   = (float*)(smem_raw + V_OFF);
    float* zbuf   = (float*)(smem_raw + Z_OFF);
    float* red    = (float*)(smem_raw + RED_OFF);   // [512]
    float* sred   = (float*)(smem_raw + SRED_OFF);  // [32][32]
    float* s1     = (float*)(smem_raw + S1_OFF);    // [4][32]
    __half* wiou  = (__half*)(smem_raw + WIOU_OFF); // [256][64] d-major
    __half* wcou  = (__half*)(smem_raw + WCOU_OFF); // [256][32] d-major
    const __half2* wiou2 = (const __half2*)wiou;
    const __half2* wcou2 = (const __half2*)wcou;

    const int t = threadIdx.x;
    const int rank = blockIdx.x % CLUSTER;
    const int b = blockIdx.x / CLUSTER;

    // skip-one aggregation into sred
    auto sgemv = [&](const float* rowp, int skip) {
        int c4 = (t & 7) * 4, g = t >> 3;
        float4 acc = make_float4(0.f, 0.f, 0.f, 0.f);
        #pragma unroll
        for (int jj = 0; jj < 16; jj++) {
            int r = g + 32 * jj;
            if (r != skip) {
                float rv = rowp[r];
                float4 hv = *(const float4*)&h_sm[r * CHUNK + c4];
                acc.x += rv * hv.x; acc.y += rv * hv.y;
                acc.z += rv * hv.z; acc.w += rv * hv.w;
            }
        }
        *(float4*)&sred[g * CHUNK + c4] = acc;
    };

    // ---- init: h chunk, fp16 weight slices, rows 0/1 ----
    {
        const float* src = h_e + (size_t)b * N_ * D_ + rank * CHUNK;
        for (int idx = t; idx < N_ * CHUNK; idx += MTHREADS) {
            int j = idx / CHUNK, c = idx % CHUNK;
            h_sm[j * CHUNK + c] = src[(size_t)j * D_ + c];
        }
        const float* ws = W_iouh + (size_t)(rank * IOU_ROWS) * D_;
        for (int idx = t; idx < IOU_ROWS * D_; idx += MTHREADS) {
            int p = idx / D_, d = idx % D_;
            wiou[d * IOU_ROWS + p] = __float2half(ws[idx]);
        }
        const float* wc = W_couh + (size_t)(rank * COU_ROWS) * D_;
        for (int idx = t; idx < COU_ROWS * D_; idx += MTHREADS) {
            int p = idx / D_, d = idx % D_;
            wcou[d * COU_ROWS + p] = __float2half(wc[idx]);
        }
        if (t < 128) {
            *(float4*)&row_sm[t * 4] =
                *(const float4*)&g_normT[((size_t)b * N_) * N_ + t * 4];
            *(float4*)&row_sm[512 + t * 4] =
                *(const float4*)&g_normT[((size_t)b * N_ + 1) * N_ + t * 4];
        }
    }
    __syncthreads();

    float pre = 0.f, pre2 = 0.f;

    // ---- bootstrap: x_par_0 ----
    sgemv(&row_sm[0], -1);
    __syncthreads();
    if (t < 128) {
        int c = t & 31, q = t >> 5;
        float s = 0.f;
        #pragma unroll
        for (int k = 0; k < 8; k++) s += sred[(q * 8 + k) * CHUNK + c];
        s1[q * CHUNK + c] = s;
    }
    __syncthreads();
    if (t < CHUNK) {
        float s = s1[t] + s1[32 + t] + s1[64 + t] + s1[96 + t];
        bcast_f32(&xpar[rank * CHUNK + t], s);
    }
    cluster_arrive();
    if (t < IOU_ROWS)
        pre = g_pre_iou[((size_t)b * N_) * (2 * D_) + rank * IOU_ROWS + t];
    if (t < COU_ROWS)
        pre2 = g_pre_cou[((size_t)b * N_) * D_ + rank * COU_ROWS + t];
    cluster_wait();

    for (int i = 0; i < N_; i++) {
        const int cur = i & 1;
        const int nxt = cur ^ 1;
        const float* xp_cur = &xpar[cur * D_];
        const float* nrow = &row_sm[nxt * N_];  // row_{i+1}

        // ---- phase 2: iou GEMV (fp16 weights, fp32 acc, float4 x loads) ----
        {
            int pp = t & 31, q = t >> 5;  // 8 d-groups of 32
            float a0 = 0.f, a1 = 0.f;
            const float* xp = xp_cur + q * 32;
            #pragma unroll
            for (int d4 = 0; d4 < 8; d4++) {
                float4 xv = *(const float4*)&xp[d4 * 4];
                #pragma unroll
                for (int k = 0; k < 4; k++) {
                    float xs = (&xv.x)[k];
                    float2 wf = __half22float2(wiou2[(q * 32 + d4 * 4 + k) * 32 + pp]);
                    a0 += xs * wf.x; a1 += xs * wf.y;
                }
            }
            *(float2*)&red[q * IOU_ROWS + 2 * pp] = make_float2(a0, a1);
        }
        __syncthreads();
        if (t < IOU_ROWS) {
            float s = pre;
            #pragma unroll
            for (int q = 0; q < 8; q++) s += red[q * IOU_ROWS + t];
            float sg = fast_sigmoid(s);
            if (rank < 4) {
                int gp = rank * IOU_ROWS + t;
                bcast_f32(&vbuf[gp], xp_cur[gp] * sg);
            } else {
                bcast_f32(&zbuf[(rank - 4) * IOU_ROWS + t], sg);
            }
        }
        cluster_arrive();
        // hide the big aggregation for x_par_{i+1} behind barrier 2
        if (i + 1 < N_) sgemv(nrow, i);
        cluster_wait();  // v, z visible cluster-wide
        __syncthreads();  // sred (gap writes) visible CTA-wide

        // ---- phase 3 GEMV (t<128, float4 v loads) ∥ s1 sred-reduce (t>=128) ----
        if (t < 128) {
            int pp = t & 15, q = t >> 4;
            float a0 = 0.f, a1 = 0.f;
            const float* vp = &vbuf[q * 32];
            #pragma unroll
            for (int d4 = 0; d4 < 8; d4++) {
                float4 vv = *(const float4*)&vp[d4 * 4];
                #pragma unroll
                for (int k = 0; k < 4; k++) {
                    float vs = (&vv.x)[k];
                    float2 wf = __half22float2(wcou2[(q * 32 + d4 * 4 + k) * 16 + pp]);
                    a0 += vs * wf.x; a1 += vs * wf.y;
                }
            }
            *(float2*)&red[q * COU_ROWS + 2 * pp] = make_float2(a0, a1);
        } else {
            int tt = t - 128;
            int c = tt & 31, q = tt >> 5;
            float s = 0.f;
            #pragma unroll
            for (int k = 0; k < 8; k++) s += sred[(q * 8 + k) * CHUNK + c];
            s1[q * CHUNK + c] = s;
        }
        __syncthreads();

        // ---- fused finish: cou sum + tanh + h update + xpar_{i+1} bcast ----
        if (t < COU_ROWS) {
            float s = pre2;
            #pragma unroll
            for (int q = 0; q < 8; q++) s += red[q * COU_ROWS + t];
            float hc  = fast_tanh(s);
            float xpv = xp_cur[rank * COU_ROWS + t];
            float zz  = zbuf[rank * COU_ROWS + t];
            float hn  = zz * xpv + (1.f - zz) * hc;
            h_sm[i * CHUNK + t] = hn;
            out[((size_t)b * N_ + i) * D_ + rank * COU_ROWS + t] = hn;
            if (i + 1 < N_) {
                float sx = s1[t] + s1[32 + t] + s1[64 + t] + s1[96 + t]
                         + nrow[i] * hn;
                bcast_f32(&xpar[nxt * D_ + rank * CHUNK + t], sx);
            }
        }

        if (i + 1 < N_) {
            cluster_arrive();
            if (t < IOU_ROWS)
                pre = g_pre_iou[((size_t)b * N_ + i + 1) * (2 * D_) + rank * IOU_ROWS + t];
            if (t < COU_ROWS)
                pre2 = g_pre_cou[((size_t)b * N_ + i + 1) * D_ + rank * COU_ROWS + t];
            if (i + 2 < N_ && t < 128)
                *(float4*)&row_sm[cur * N_ + t * 4] =
                    *(const float4*)&g_normT[((size_t)b * N_ + i + 2) * N_ + t * 4];
            cluster_wait();  // x_par_{i+1} (and h row i) visible cluster-wide
        }
    }
}

extern "C" void kernel_launch(void* const* d_in, const int* in_sizes, int n_in,
                              void* d_out, int out_size) {
    const float* h_e    = (const float*)d_in[0];
    const float* adj    = (const float*)d_in[1];
    const float* W_ioux = (const float*)d_in[2];
    const float* b_ioux = (const float*)d_in[3];
    const float* W_iouh = (const float*)d_in[4];
    const float* b_iouh = (const float*)d_in[5];
    const float* W_coux = (const float*)d_in[6];
    const float* b_coux = (const float*)d_in[7];
    const float* W_couh = (const float*)d_in[8];
    const float* b_couh = (const float*)d_in[9];
    float* out = (float*)d_out;

    static cudaStream_t s2 = nullptr;
    static cudaEvent_t ev_fork = nullptr, ev_join = nullptr;
    static bool init_done = false;
    if (!init_done) {
        cudaStreamCreateWithFlags(&s2, cudaStreamNonBlocking);
        cudaEventCreateWithFlags(&ev_fork, cudaEventDisableTiming);
        cudaEventCreateWithFlags(&ev_join, cudaEventDisableTiming);
        cudaFuncSetAttribute(k_main, cudaFuncAttributeMaxDynamicSharedMemorySize,
                             SMEM_BYTES);
        init_done = true;
    }

    cudaEventRecord(ev_fork, 0);
    cudaStreamWaitEvent(s2, ev_fork, 0);
    {
        dim3 grid(6, (B_ * N_) / 128);   // blocks 0-3: iou, 4-5: cou
        k_gemm_fused<<<grid, 256, 0, s2>>>(h_e, W_ioux, b_ioux, b_iouh,
                                           W_coux, b_coux, b_couh);
    }
    k_dinv<<<B_ * N_, 256>>>(adj);
    {
        dim3 grid(N_ / 32, N_ / 32, B_), blk(32, 8);
        k_transpose<<<grid, blk>>>(adj);
    }
    cudaEventRecord(ev_join, s2);
    cudaStreamWaitEvent(0, ev_join, 0);

    k_main<<<B_ * CLUSTER, MTHREADS, SMEM_BYTES>>>(h_e, W_iouh, W_couh, out);
}